// round 12
// baseline (speedup 1.0000x reference)
#include <cuda_runtime.h>

#define BB 8
#define LL 2048
#define DD 2048
#define NN 16
#define ROWS (BB*LL)
#define CS 32
#define CPB (LL/CS)
#define NCHUNK (ROWS/CS)

__device__ float g_delta[ROWS];
__device__ float g_Bt[ROWS*NN];
__device__ float g_Ct[ROWS*NN];
__device__ float g_Dt[ROWS];
__device__ float g_Ad[(size_t)ROWS*NN*NN];
__device__ float g_cP[NCHUNK*NN*NN];
__device__ float g_cq[NCHUNK*NN];
__device__ float g_cS[NCHUNK*NN];
__device__ float g_V[ROWS*NN];      // v_t = P_t^T Ct_t
__device__ float g_C[ROWS];         // c_t = Ct_t . q_t + Dt_t
__device__ __align__(16) float2 g_Wp[40*2048];  // hi/lo tf32 split of [Wb;Wc;Wd;dp;0..]

__device__ __forceinline__ unsigned s2u(const void* p) {
    unsigned a;
    asm("{ .reg .u64 t; cvta.to.shared.u64 t, %1; cvt.u32.u64 %0, t; }" : "=r"(a) : "l"(p));
    return a;
}
#define CP16(d, s) asm volatile("cp.async.ca.shared.global [%0], [%1], 16;\n" :: "r"(d), "l"(s))
#define CP4(d, s)  asm volatile("cp.async.ca.shared.global [%0], [%1], 4;\n"  :: "r"(d), "l"(s))
#define CPCOMMIT() asm volatile("cp.async.commit_group;\n")
#define CPWAIT1()  asm volatile("cp.async.wait_group 1;\n")

__device__ __forceinline__ unsigned tf32b(float x) {
    unsigned y;
    asm("cvt.rna.tf32.f32 %0, %1;" : "=r"(y) : "f"(x));
    return y;
}
__device__ __forceinline__ float tf32f(float x) {
    return __uint_as_float(tf32b(x));
}
__device__ __forceinline__ void mma8(float c[4], unsigned a0, unsigned a1,
                                     unsigned a2, unsigned a3,
                                     unsigned b0, unsigned b1) {
    asm volatile(
        "mma.sync.aligned.m16n8k8.row.col.f32.tf32.tf32.f32 "
        "{%0,%1,%2,%3}, {%4,%5,%6,%7}, {%8,%9}, {%0,%1,%2,%3};"
        : "+f"(c[0]), "+f"(c[1]), "+f"(c[2]), "+f"(c[3])
        : "r"(a0), "r"(a1), "r"(a2), "r"(a3), "r"(b0), "r"(b1));
}

// ---------------- K0: split W into tf32 hi/lo pairs ----------------
__global__ __launch_bounds__(256) void k0_wsplit(
    const float* __restrict__ Wb, const float* __restrict__ Wc,
    const float* __restrict__ Wd, const float* __restrict__ dp)
{
    int idx = blockIdx.x * 256 + threadIdx.x;
    int r = idx >> 11, c = idx & 2047;
    float v = 0.f;
    if (r < 16)       v = Wb[r * DD + c];
    else if (r < 32)  v = Wc[(r - 16) * DD + c];
    else if (r == 32) v = Wd[c];
    else if (r == 33) v = dp[c];
    float h = tf32f(v);
    g_Wp[idx] = make_float2(h, tf32f(v - h));
}

// ---------------- K1: tf32x3 tensor-core projections, cp.async staged ------
__global__ __launch_bounds__(128) void k1_proj(
    const float* __restrict__ u,
    const float* __restrict__ bb, const float* __restrict__ bc,
    const float* __restrict__ bd)
{
    __shared__ float  sUraw[2][64 * 36];
    __shared__ float2 sW[2][40 * 36];
    const int tid = threadIdx.x;
    const int w = tid >> 5, lane = tid & 31;
    const int g = lane >> 2, t = lane & 3;
    const int row0 = blockIdx.x * 64;
    const int wrow = w * 16;

    const unsigned su0 = s2u(&sUraw[0][0]);
    const unsigned sw0 = s2u(&sW[0][0]);

    auto issueK = [&](int bi, int kc) {
        unsigned du = su0 + bi * (64 * 36) * 4;
#pragma unroll
        for (int j = 0; j < 4; j++) {
            int idx = tid + 128 * j;
            int r = idx >> 3, c4 = idx & 7;
            CP16(du + (r * 36 + c4 * 4) * 4,
                 u + (size_t)(row0 + r) * DD + kc * 32 + c4 * 4);
        }
        unsigned dw = sw0 + bi * (40 * 36) * 8;
#pragma unroll
        for (int j = 0; j < 5; j++) {
            int idx = tid + 128 * j;
            int r = idx >> 4, q = idx & 15;
            CP16(dw + (r * 36 + q * 2) * 8, &g_Wp[r * 2048 + kc * 32 + q * 2]);
        }
    };

    float acc[5][4];
#pragma unroll
    for (int n = 0; n < 5; n++)
#pragma unroll
        for (int m = 0; m < 4; m++) acc[n][m] = 0.f;

    issueK(0, 0); CPCOMMIT();
    issueK(1, 1); CPCOMMIT();

    for (int kc = 0; kc < 64; kc++) {
        CPWAIT1();
        __syncthreads();
        const int bi = kc & 1;
        const float*  Ub = &sUraw[bi][0];
        const float2* Wb2 = &sW[bi][0];
#pragma unroll
        for (int ks = 0; ks < 4; ks++) {
            int k = ks * 8;
            float a0 = Ub[(wrow + g) * 36 + k + t];
            float a1 = Ub[(wrow + g + 8) * 36 + k + t];
            float a2 = Ub[(wrow + g) * 36 + k + t + 4];
            float a3 = Ub[(wrow + g + 8) * 36 + k + t + 4];
            unsigned ah0 = tf32b(a0), ah1 = tf32b(a1), ah2 = tf32b(a2), ah3 = tf32b(a3);
            unsigned al0 = tf32b(a0 - __uint_as_float(ah0));
            unsigned al1 = tf32b(a1 - __uint_as_float(ah1));
            unsigned al2 = tf32b(a2 - __uint_as_float(ah2));
            unsigned al3 = tf32b(a3 - __uint_as_float(ah3));
#pragma unroll
            for (int nt = 0; nt < 5; nt++) {
                float2 b0p = Wb2[(nt * 8 + g) * 36 + k + t];
                float2 b1p = Wb2[(nt * 8 + g) * 36 + k + t + 4];
                unsigned bh0 = __float_as_uint(b0p.x), bl0 = __float_as_uint(b0p.y);
                unsigned bh1 = __float_as_uint(b1p.x), bl1 = __float_as_uint(b1p.y);
                mma8(acc[nt], ah0, ah1, ah2, ah3, bh0, bh1);
                mma8(acc[nt], ah0, ah1, ah2, ah3, bl0, bl1);
                mma8(acc[nt], al0, al1, al2, al3, bh0, bh1);
            }
        }
        __syncthreads();
        if (kc + 2 < 64) issueK(bi, kc + 2);
        CPCOMMIT();
    }
    const int rlo = row0 + wrow + g, rhi = rlo + 8;
#pragma unroll
    for (int nt = 0; nt < 5; nt++) {
#pragma unroll
        for (int m = 0; m < 4; m++) {
            int row = (m & 2) ? rhi : rlo;
            int col = nt * 8 + 2 * t + (m & 1);
            float v = acc[nt][m];
            if (col < 16)       g_Bt[row * NN + col] = v + bb[col];
            else if (col < 32)  g_Ct[row * NN + col - 16] = v + bc[col - 16];
            else if (col == 32) g_Dt[row] = v + bd[0];
            else if (col == 33) g_delta[row] = 1.f / (1.f + __expf(-v));
        }
    }
}

// ---------------- K2: batched expm (PS deg-9, 1 squaring, 5 matmuls) -------
#define C3f 1.6666667e-1f
#define C4f 4.1666668e-2f
#define C5f 8.3333333e-3f
#define C6f 1.3888889e-3f
#define C7f 1.9841270e-4f
#define C8f 2.4801587e-5f
#define C9f 2.7557319e-6f

__device__ __forceinline__ void mm16(const float* __restrict__ A,
                                     const float* __restrict__ Bm,
                                     int i0, int j0, float c[4][4])
{
#pragma unroll
    for (int r = 0; r < 4; r++)
#pragma unroll
        for (int q = 0; q < 4; q++) c[r][q] = 0.f;
#pragma unroll
    for (int k = 0; k < 16; k++) {
        float b0 = Bm[k * 17 + j0 + 0];
        float b1 = Bm[k * 17 + j0 + 1];
        float b2 = Bm[k * 17 + j0 + 2];
        float b3 = Bm[k * 17 + j0 + 3];
#pragma unroll
        for (int r = 0; r < 4; r++) {
            float a = A[(i0 + r) * 17 + k];
            c[r][0] = fmaf(a, b0, c[r][0]);
            c[r][1] = fmaf(a, b1, c[r][1]);
            c[r][2] = fmaf(a, b2, c[r][2]);
            c[r][3] = fmaf(a, b3, c[r][3]);
        }
    }
}

__global__ __launch_bounds__(128) void k2_expm(const float* __restrict__ Ag)
{
    __shared__ float sm[8 * 1360];
    const int tid = threadIdx.x;
    const int mat = tid >> 4, q = tid & 15;
    const int i0 = (q >> 2) * 4, j0 = (q & 3) * 4;
    const int id0 = blockIdx.x * 8 + mat;
    const int t = id0 & (LL - 1);
    const float sd = 0.5f * g_delta[id0];

    float* Mb = sm + mat * 1360;
    float* M2b = Mb + 272;
    float* M3b = Mb + 544;
    float* T1 = Mb + 816;
    float* T2 = Mb + 1088;

    const float4* Ar = reinterpret_cast<const float4*>(Ag + (size_t)t * 256 + q * 16);
    float4 v0 = Ar[0], v1 = Ar[1], v2 = Ar[2], v3 = Ar[3];
    float* dst = Mb + q * 17;
    dst[0] = v0.x * sd;  dst[1] = v0.y * sd;  dst[2] = v0.z * sd;  dst[3] = v0.w * sd;
    dst[4] = v1.x * sd;  dst[5] = v1.y * sd;  dst[6] = v1.z * sd;  dst[7] = v1.w * sd;
    dst[8] = v2.x * sd;  dst[9] = v2.y * sd;  dst[10] = v2.z * sd; dst[11] = v2.w * sd;
    dst[12] = v3.x * sd; dst[13] = v3.y * sd; dst[14] = v3.z * sd; dst[15] = v3.w * sd;
    __syncwarp();

    float c[4][4];
    mm16(Mb, Mb, i0, j0, c);                 // M2
#pragma unroll
    for (int r = 0; r < 4; r++)
#pragma unroll
        for (int cc = 0; cc < 4; cc++) M2b[(i0 + r) * 17 + j0 + cc] = c[r][cc];
    __syncwarp();
    mm16(M2b, Mb, i0, j0, c);                // M3
#pragma unroll
    for (int r = 0; r < 4; r++)
#pragma unroll
        for (int cc = 0; cc < 4; cc++) M3b[(i0 + r) * 17 + j0 + cc] = c[r][cc];
    __syncwarp();
#pragma unroll
    for (int r = 0; r < 4; r++)              // T1 = b2
#pragma unroll
        for (int cc = 0; cc < 4; cc++) {
            int idx = (i0 + r) * 17 + j0 + cc;
            float val = C7f * Mb[idx] + C8f * M2b[idx] + C9f * M3b[idx];
            if (i0 + r == j0 + cc) val += C6f;
            T1[idx] = val;
        }
    __syncwarp();
    mm16(M3b, T1, i0, j0, c);                // T2 = M3*b2 + b1
#pragma unroll
    for (int r = 0; r < 4; r++)
#pragma unroll
        for (int cc = 0; cc < 4; cc++) {
            int idx = (i0 + r) * 17 + j0 + cc;
            float val = c[r][cc] + C4f * Mb[idx] + C5f * M2b[idx];
            if (i0 + r == j0 + cc) val += C3f;
            T2[idx] = val;
        }
    __syncwarp();
    mm16(M3b, T2, i0, j0, c);                // T1 = T9(M/2)
#pragma unroll
    for (int r = 0; r < 4; r++)
#pragma unroll
        for (int cc = 0; cc < 4; cc++) {
            int idx = (i0 + r) * 17 + j0 + cc;
            float val = c[r][cc] + Mb[idx] + 0.5f * M2b[idx];
            if (i0 + r == j0 + cc) val += 1.f;
            T1[idx] = val;
        }
    __syncwarp();
    mm16(T1, T1, i0, j0, c);                 // single squaring -> Ad
    size_t ob = (size_t)id0 * 256;
#pragma unroll
    for (int r = 0; r < 4; r++)
        *reinterpret_cast<float4*>(g_Ad + ob + (i0 + r) * 16 + j0) =
            make_float4(c[r][0], c[r][1], c[r][2], c[r][3]);
}

// ---------------- scan1: per-chunk (P,q) + per-row (v,c), cp.async ----------
// per-warp smem: P0[272] P1[272] qb[32] AdB[2][356]
//   AdB buf: Ad 16 rows x stride 20 (=320), Bt[16] @320, Ct[16] @336, Dt @352
#define S1C 356
#define S1W (272 + 272 + 32 + 2*S1C)
__global__ __launch_bounds__(64) void k_scan1()
{
    __shared__ float sm[2 * S1W];
    const int warp = threadIdx.x >> 5, lane = threadIdx.x & 31;
    const int chunk = blockIdx.x * 2 + warp;
    float* base = sm + warp * S1W;
    float* P0 = base;
    float* P1 = base + 272;
    float* qb = base + 544;
    float* AdB = base + 576;

    for (int i = lane; i < 272; i += 32) {
        int r = i / 17, col = i % 17;
        P0[i] = (col < 16 && r == col) ? 1.f : 0.f;
    }
    if (lane < 16) qb[lane] = 0.f;

    const unsigned adu = s2u(AdB);
    const size_t row0 = (size_t)chunk * CS;

    auto issue = [&](int bi, size_t rr) {
        unsigned d = adu + bi * S1C * 4;
#pragma unroll
        for (int j = 0; j < 2; j++) {
            int f = lane + 32 * j;
            int r = f >> 2, c = (f & 3) << 2;
            CP16(d + (r * 20 + c) * 4, g_Ad + rr * 256 + f * 4);
        }
        if (lane < 4)       CP16(d + (320 + lane * 4) * 4,       g_Bt + rr * 16 + lane * 4);
        else if (lane < 8)  CP16(d + (336 + (lane - 4) * 4) * 4, g_Ct + rr * 16 + (lane - 4) * 4);
        else if (lane == 8) CP4(d + 352 * 4, g_Dt + rr);
    };

    issue(0, row0); CPCOMMIT();
    issue(1, row0 + 1); CPCOMMIT();

    const int i0 = (lane >> 2) * 2, j0 = (lane & 3) * 4;
    float* Pc = P0; float* Pn = P1;
    int qc = 0;
    for (int tt = 0; tt < CS; tt++) {
        CPWAIT1();
        __syncwarp();
        const float* Ab = AdB + (tt & 1) * S1C;
        // ---- P update (all 32 lanes, 2x4 tile each) ----
        float c0[4] = {0, 0, 0, 0}, c1[4] = {0, 0, 0, 0};
#pragma unroll
        for (int k = 0; k < 16; k++) {
            float a0 = Ab[i0 * 20 + k], a1 = Ab[(i0 + 1) * 20 + k];
            float b0 = Pc[k * 17 + j0 + 0];
            float b1 = Pc[k * 17 + j0 + 1];
            float b2 = Pc[k * 17 + j0 + 2];
            float b3 = Pc[k * 17 + j0 + 3];
            c0[0] = fmaf(a0, b0, c0[0]); c0[1] = fmaf(a0, b1, c0[1]);
            c0[2] = fmaf(a0, b2, c0[2]); c0[3] = fmaf(a0, b3, c0[3]);
            c1[0] = fmaf(a1, b0, c1[0]); c1[1] = fmaf(a1, b1, c1[1]);
            c1[2] = fmaf(a1, b2, c1[2]); c1[3] = fmaf(a1, b3, c1[3]);
        }
#pragma unroll
        for (int m = 0; m < 4; m++) {
            Pn[i0 * 17 + j0 + m] = c0[m];
            Pn[(i0 + 1) * 17 + j0 + m] = c1[m];
        }
        // ---- q update + c = Ct.q + Dt (lower 16 lanes) ----
        if (lane < 16) {
            float sn = Ab[320 + lane];
            const float* ar = Ab + lane * 20;
            const float* qo = qb + qc * 16;
#pragma unroll
            for (int k = 0; k < 16; k++) sn = fmaf(ar[k], qo[k], sn);
            qb[(qc ^ 1) * 16 + lane] = sn;
            float p = Ab[336 + lane] * sn;
            p += __shfl_xor_sync(0x0000ffffu, p, 8, 16);
            p += __shfl_xor_sync(0x0000ffffu, p, 4, 16);
            p += __shfl_xor_sync(0x0000ffffu, p, 2, 16);
            p += __shfl_xor_sync(0x0000ffffu, p, 1, 16);
            if (lane == 0) g_C[row0 + tt] = p + Ab[352];
        }
        __syncwarp();   // Pn + q visible
        // ---- v = Pn^T Ct (upper 16 lanes, column dot) ----
        if (lane >= 16) {
            int j = lane - 16;
            float v = 0.f;
#pragma unroll
            for (int i = 0; i < 16; i++) v = fmaf(Ab[336 + i], Pn[i * 17 + j], v);
            g_V[(row0 + tt) * 16 + j] = v;
        }
        __syncwarp();   // all Ab reads done before overwrite
        if (tt + 2 < CS) issue(tt & 1, row0 + tt + 2);
        CPCOMMIT();
        float* tmp = Pc; Pc = Pn; Pn = tmp;
        qc ^= 1;
    }
#pragma unroll
    for (int m = 0; m < 4; m++) {
        g_cP[chunk * 256 + i0 * 16 + j0 + m] = Pc[i0 * 17 + j0 + m];
        g_cP[chunk * 256 + (i0 + 1) * 16 + j0 + m] = Pc[(i0 + 1) * 17 + j0 + m];
    }
    if (lane < 16) g_cq[chunk * 16 + lane] = qb[qc * 16 + lane];
}

// ---------------- scan2: bulk-stage 32 chunks to smem, warp0 scans ----------
__global__ __launch_bounds__(512) void k_scan2()
{
    __shared__ float Ps[32][272];
    __shared__ float qs[32][16];
    const int tid = threadIdx.x;
    const int b = blockIdx.x;
    const int lane = tid & 31;
    float s = 0.f;

    for (int h = 0; h < 2; h++) {
        const int cbase = b * CPB + h * 32;
        for (int i = tid; i < 32 * 256; i += 512) {
            int ch = i >> 8, f = i & 255;
            int r = f >> 4, cc = f & 15;
            Ps[ch][r * 17 + cc] = g_cP[(size_t)(cbase + ch) * 256 + f];
        }
        {
            int ch = tid >> 4;
            if (ch < 32) qs[ch][tid & 15] = g_cq[(cbase + ch) * 16 + (tid & 15)];
        }
        __syncthreads();
        if (tid < 32 && lane < 16) {
            for (int ci = 0; ci < 32; ci++) {
                g_cS[(cbase + ci) * 16 + lane] = s;
                const float* prow = &Ps[ci][lane * 17];
                float a0 = 0.f, a1 = 0.f, a2 = 0.f, a3 = 0.f;
#pragma unroll
                for (int k = 0; k < 4; k++) {
                    a0 = fmaf(prow[k],      __shfl_sync(0xffffu, s, k,      16), a0);
                    a1 = fmaf(prow[k + 4],  __shfl_sync(0xffffu, s, k + 4,  16), a1);
                    a2 = fmaf(prow[k + 8],  __shfl_sync(0xffffu, s, k + 8,  16), a2);
                    a3 = fmaf(prow[k + 12], __shfl_sync(0xffffu, s, k + 12, 16), a3);
                }
                s = ((a0 + a1) + (a2 + a3)) + qs[ci][lane];
            }
        }
        __syncthreads();
    }
}

// ---------------- k_out: y = v . s0 + c ------------------------------------
__global__ __launch_bounds__(256) void k_out(float* __restrict__ y)
{
    const int row = blockIdx.x * 256 + threadIdx.x;
    const int ch = row >> 5;
    const float4* vr = reinterpret_cast<const float4*>(g_V + (size_t)row * 16);
    float4 v0 = vr[0], v1 = vr[1], v2 = vr[2], v3 = vr[3];
    const float4* sr = reinterpret_cast<const float4*>(g_cS + ch * 16);
    float4 s0 = sr[0], s1 = sr[1], s2 = sr[2], s3 = sr[3];
    float a = g_C[row];
    a = fmaf(v0.x, s0.x, a); a = fmaf(v0.y, s0.y, a);
    a = fmaf(v0.z, s0.z, a); a = fmaf(v0.w, s0.w, a);
    a = fmaf(v1.x, s1.x, a); a = fmaf(v1.y, s1.y, a);
    a = fmaf(v1.z, s1.z, a); a = fmaf(v1.w, s1.w, a);
    a = fmaf(v2.x, s2.x, a); a = fmaf(v2.y, s2.y, a);
    a = fmaf(v2.z, s2.z, a); a = fmaf(v2.w, s2.w, a);
    a = fmaf(v3.x, s3.x, a); a = fmaf(v3.y, s3.y, a);
    a = fmaf(v3.z, s3.z, a); a = fmaf(v3.w, s3.w, a);
    y[row] = a;
}

extern "C" void kernel_launch(void* const* d_in, const int* in_sizes, int n_in,
                              void* d_out, int out_size)
{
    const float* u  = (const float*)d_in[0];
    const float* A  = (const float*)d_in[1];
    const float* dp = (const float*)d_in[2];
    const float* Wb = (const float*)d_in[3];
    const float* bb = (const float*)d_in[4];
    const float* Wc = (const float*)d_in[5];
    const float* bc = (const float*)d_in[6];
    const float* Wd = (const float*)d_in[7];
    const float* bd = (const float*)d_in[8];
    float* y = (float*)d_out;

    k0_wsplit<<<(40 * 2048) / 256, 256>>>(Wb, Wc, Wd, dp);
    k1_proj<<<ROWS / 64, 128>>>(u, bb, bc, bd);
    k2_expm<<<ROWS / 8, 128>>>(A);
    k_scan1<<<NCHUNK / 2, 64>>>();
    k_scan2<<<BB, 512>>>();
    k_out<<<ROWS / 256, 256>>>(y);
}